// round 13
// baseline (speedup 1.0000x reference)
#include <cuda_runtime.h>
#include <cuda_bf16.h>
#include <math.h>
#include <stdint.h>

#define SQ   1024
#define DM   2048
#define NH   32
#define NBLK 16
#define NE   4
#define DF   8192
#define VOC  50257
#define QKVN 6144

// ---------------- scratch ----------------
__device__ float g_x  [SQ*DM];
__device__ float g_qkv[SQ*QKVN];
__device__ float g_x1 [SQ*DM];
__device__ float g_x2 [SQ*DM];
__device__ float g_cos[SQ*32];
__device__ float g_sin[SQ*32];
__device__ int   g_cnt[NE];
__device__ int   g_etok[NE*SQ];
__device__ int   g_tok_slot[SQ*2];
__device__ float g_tok_w  [SQ*2];
__device__ float g_h1[NE*SQ*DF];
__device__ float g_y [NE*SQ*DM];
__device__ float g_aux;

__device__ __align__(16) __nv_bfloat16 g_xh [SQ*DM],  g_xl [SQ*DM];
__device__ __align__(16) __nv_bfloat16 g_ath[SQ*DM],  g_atl[SQ*DM];
__device__ __align__(16) __nv_bfloat16 g_x2h[SQ*DM],  g_x2l[SQ*DM];
__device__ __align__(16) __nv_bfloat16 g_x3h[SQ*DM],  g_x3l[SQ*DM];
__device__ __align__(16) __nv_bfloat16 g_hh [NE*SQ*DF], g_hl[NE*SQ*DF];

// ---------------- helpers ----------------
__device__ __forceinline__ uint32_t s2u(const void* p) {
    uint32_t a;
    asm("{ .reg .u64 t; cvta.to.shared.u64 t, %1; cvt.u32.u64 %0, t; }" : "=r"(a) : "l"(p));
    return a;
}
__device__ __forceinline__ void cpa16(uint32_t dst, const void* src, int sz) {
    asm volatile("cp.async.cg.shared.global [%0], [%1], 16, %2;" :: "r"(dst), "l"(src), "r"(sz) : "memory");
}
#define CPA_COMMIT() asm volatile("cp.async.commit_group;" ::: "memory")

__device__ __forceinline__ void ldsm4(uint32_t* r, uint32_t addr) {
    asm volatile("ldmatrix.sync.aligned.m8n8.x4.shared.b16 {%0,%1,%2,%3}, [%4];"
        : "=r"(r[0]), "=r"(r[1]), "=r"(r[2]), "=r"(r[3]) : "r"(addr));
}
__device__ __forceinline__ void mma16816(float* d, const uint32_t* a, const uint32_t* b) {
    asm volatile("mma.sync.aligned.m16n8k16.row.col.f32.bf16.bf16.f32 "
        "{%0,%1,%2,%3}, {%4,%5,%6,%7}, {%8,%9}, {%0,%1,%2,%3};"
        : "+f"(d[0]), "+f"(d[1]), "+f"(d[2]), "+f"(d[3])
        : "r"(a[0]), "r"(a[1]), "r"(a[2]), "r"(a[3]), "r"(b[0]), "r"(b[1]));
}
__device__ __forceinline__ void split2(float v, __nv_bfloat16* h, __nv_bfloat16* l) {
    __nv_bfloat16 hh = __float2bfloat16(v);
    *h = hh;
    *l = __float2bfloat16(v - __bfloat162float(hh));
}
__device__ __forceinline__ float block_sum_256(float v, float* sm) {
    __syncthreads();
    #pragma unroll
    for (int o = 16; o > 0; o >>= 1) v += __shfl_down_sync(0xffffffffu, v, o);
    if ((threadIdx.x & 31) == 0) sm[threadIdx.x >> 5] = v;
    __syncthreads();
    float r = 0.f;
    if (threadIdx.x < 8) {
        r = sm[threadIdx.x];
        #pragma unroll
        for (int o = 4; o > 0; o >>= 1) r += __shfl_down_sync(0x000000ffu, r, o);
        if (threadIdx.x == 0) sm[0] = r;
    }
    __syncthreads();
    return sm[0];
}

// ---------------- mma.sync bf16x3 GEMM, B read as fp32 + in-kernel split ----------------
// C[m][n] = sum_k A[m][k]*B[n][k]. CTA tile 128x128, K-chunk 64, 2-stage,
// A: bf16 hi/lo via cp.async; B: fp32 LDG -> reg prefetch -> split -> smem.
#define GSMEM_BYTES (2*65536 + 1024)

#define ISSUE_A(KT, ST) do {                                                   \
    uint32_t bb_ = base + (uint32_t)(ST) * 65536u;                             \
    long k0_ = (long)(KT) * 64;                                                \
    _Pragma("unroll")                                                          \
    for (int u = tid; u < 1024; u += 256) {                                    \
        int r_ = u >> 3, kc_ = u & 7;                                          \
        uint32_t smo_ = (uint32_t)(r_ * 128 + ((kc_ ^ (r_ & 7)) << 4));        \
        int rv_ = rowsm[r_];                                                   \
        int okA_ = (rv_ >= 0) ? 16 : 0;                                        \
        long ga_ = ((rv_ >= 0) ? (long)rv_ : 0) * (long)K + k0_ + kc_ * 8;     \
        cpa16(bb_ + smo_,          Ah + ga_, okA_);                            \
        cpa16(bb_ + 16384 + smo_,  Al + ga_, okA_);                            \
    }                                                                          \
    CPA_COMMIT();                                                              \
} while (0)

#define LOAD_B(KT) do {                                                        \
    long k0_ = (long)(KT) * 64;                                                \
    _Pragma("unroll")                                                          \
    for (int j = 0; j < 8; j++)                                                \
        breg[j] = *(const float4*)(Bp + k0_ + 4 * j);                          \
} while (0)

__global__ __launch_bounds__(256, 1)
void mma_gemm(const __nv_bfloat16* __restrict__ Ah, const __nv_bfloat16* __restrict__ Al,
              const float* __restrict__ B,
              float* __restrict__ C, const float* __restrict__ Res,
              const float* __restrict__ H1,
              __nv_bfloat16* __restrict__ Ch, __nv_bfloat16* __restrict__ Cl,
              const int* __restrict__ gatherB,
              int M, int N, int K, int ldc,
              long aStrE, long bStrE, long cStrE)
{
    extern __shared__ char dsm[];
    __shared__ int rowsm[128];

    int e = blockIdx.z;
    if (M < 0) M = g_cnt[e];
    int m0 = blockIdx.x * 128;
    if (m0 >= M) return;
    int n0 = blockIdx.y * 128;
    Ah += (long)e * aStrE; Al += (long)e * aStrE;
    B  += (long)e * bStrE;
    C  += (long)e * cStrE;
    if (H1) { H1 += (long)e * cStrE; Ch += (long)e * cStrE; Cl += (long)e * cStrE; }
    const int* gth = gatherB ? (gatherB + e * SQ) : nullptr;

    int tid = threadIdx.x, wid = tid >> 5, lane = tid & 31;
    if (tid < 128) {
        int m = m0 + tid;
        rowsm[tid] = (m < M) ? (gth ? gth[m] : m) : -1;
    }
    __syncthreads();

    char* dsb = (char*)(((uintptr_t)dsm + 1023u) & ~(uintptr_t)1023u);
    uint32_t base = s2u(dsb);

    // B prefetch mapping: 2 threads per row, 32 cols each
    int brow = tid >> 1;
    int bcol = (tid & 1) * 32;
    int bn = n0 + brow;
    const float* Bp = B + (long)((bn < N) ? bn : 0) * K + bcol;
    float4 breg[8];

    int m0w = (wid >> 1) * 32;
    int n0w = (wid & 1) * 64;
    int tq = lane >> 3, li = lane & 7;
    int rA0 = m0w + (tq & 1) * 8 + li;
    int rB0 = n0w + (tq >> 1) * 8 + li;
    int kuA = tq >> 1;
    int kuB = tq & 1;

    float acc[2][8][4];
    #pragma unroll
    for (int mt = 0; mt < 2; mt++)
        #pragma unroll
        for (int nt = 0; nt < 8; nt++)
            #pragma unroll
            for (int c = 0; c < 4; c++) acc[mt][nt][c] = 0.f;

    int nk = K >> 6;
    ISSUE_A(0, 0);
    LOAD_B(0);

    for (int kt = 0; kt < nk; kt++) {
        int st = kt & 1;
        asm volatile("cp.async.wait_group 0;" ::: "memory");
        // split+store prefetched B into this stage
        {
            char* bsm = dsb + st * 65536;
            #pragma unroll
            for (int j = 0; j < 4; j++) {
                __align__(16) __nv_bfloat16 h8[8], l8[8];
                float4 v0 = breg[2 * j], v1 = breg[2 * j + 1];
                split2(v0.x, &h8[0], &l8[0]); split2(v0.y, &h8[1], &l8[1]);
                split2(v0.z, &h8[2], &l8[2]); split2(v0.w, &h8[3], &l8[3]);
                split2(v1.x, &h8[4], &l8[4]); split2(v1.y, &h8[5], &l8[5]);
                split2(v1.z, &h8[6], &l8[6]); split2(v1.w, &h8[7], &l8[7]);
                int kc = (bcol >> 3) + j;
                uint32_t off = (uint32_t)(brow * 128 + ((kc ^ (brow & 7)) << 4));
                *(uint4*)(bsm + 32768 + off) = *(uint4*)h8;
                *(uint4*)(bsm + 49152 + off) = *(uint4*)l8;
            }
        }
        __syncthreads();
        if (kt + 1 < nk) {
            ISSUE_A(kt + 1, st ^ 1);
            LOAD_B(kt + 1);
        }

        uint32_t bb = base + (uint32_t)st * 65536u;
        #pragma unroll
        for (int ks = 0; ks < 4; ks++) {
            uint32_t ahf[2][4], alf[2][4];
            #pragma unroll
            for (int mt = 0; mt < 2; mt++) {
                int row = rA0 + mt * 16;
                uint32_t ad = bb + (uint32_t)(row * 128 + (((kuA + ks * 2) ^ (row & 7)) << 4));
                ldsm4(ahf[mt], ad);
                ldsm4(alf[mt], ad + 16384);
            }
            uint32_t bhf[4][4], blf[4][4];
            #pragma unroll
            for (int g = 0; g < 4; g++) {
                int row = rB0 + g * 16;
                uint32_t bd = bb + 32768 + (uint32_t)(row * 128 + (((kuB + ks * 2) ^ (row & 7)) << 4));
                ldsm4(bhf[g], bd);
                ldsm4(blf[g], bd + 16384);
            }
            #pragma unroll
            for (int mt = 0; mt < 2; mt++)
                #pragma unroll
                for (int g = 0; g < 4; g++)
                    #pragma unroll
                    for (int hh = 0; hh < 2; hh++) {
                        float* d = acc[mt][g * 2 + hh];
                        mma16816(d, ahf[mt], &bhf[g][hh * 2]);
                        mma16816(d, ahf[mt], &blf[g][hh * 2]);
                        mma16816(d, alf[mt], &bhf[g][hh * 2]);
                    }
        }
        __syncthreads();
    }

    // epilogue
    #pragma unroll
    for (int mt = 0; mt < 2; mt++) {
        #pragma unroll
        for (int half = 0; half < 2; half++) {
            int row = m0 + m0w + mt * 16 + (lane >> 2) + half * 8;
            if (row >= M) continue;
            long o = (long)row * ldc;
            #pragma unroll
            for (int nt = 0; nt < 8; nt++) {
                int col = n0 + n0w + nt * 8 + (lane & 3) * 2;
                float d0 = acc[mt][nt][half * 2], d1 = acc[mt][nt][half * 2 + 1];
                if (H1) {   // fused silu(h1)*acc -> bf16 split
                    if (col < N) {
                        float hv = H1[o + col];
                        float v = hv / (1.f + __expf(-hv)) * d0;
                        split2(v, &Ch[o + col], &Cl[o + col]);
                    }
                    if (col + 1 < N) {
                        float hv = H1[o + col + 1];
                        float v = hv / (1.f + __expf(-hv)) * d1;
                        split2(v, &Ch[o + col + 1], &Cl[o + col + 1]);
                    }
                } else if (Res) {
                    if (col < N)     C[o + col]     = d0 + Res[o + col];
                    if (col + 1 < N) C[o + col + 1] = d1 + Res[o + col + 1];
                } else {
                    if (col < N)     C[o + col]     = d0;
                    if (col + 1 < N) C[o + col + 1] = d1;
                }
            }
        }
    }
}

__global__ void ropetab_k() {
    int s = blockIdx.x, i = threadIdx.x;
    double inv = exp(-((double)(2 * i) / 64.0) * log(10000.0));
    double ang = (double)s * inv;
    g_cos[s * 32 + i] = (float)cos(ang);
    g_sin[s * 32 + i] = (float)sin(ang);
}

__global__ void embed_k(const int* __restrict__ tok, const float* __restrict__ emb) {
    int t = blockIdx.x;
    int row = tok[t];
    const float4* src = (const float4*)(emb + (size_t)row * DM);
    for (int i = threadIdx.x; i < DM / 4; i += blockDim.x) {
        float4 v = src[i];
        *(float4*)(g_x + (size_t)t * DM + 4 * i) = v;
        __align__(8) __nv_bfloat16 h[4], l[4];
        split2(v.x, &h[0], &l[0]); split2(v.y, &h[1], &l[1]);
        split2(v.z, &h[2], &l[2]); split2(v.w, &h[3], &l[3]);
        *reinterpret_cast<uint2*>(g_xh + (size_t)t * DM + 4 * i) = *reinterpret_cast<uint2*>(h);
        *reinterpret_cast<uint2*>(g_xl + (size_t)t * DM + 4 * i) = *reinterpret_cast<uint2*>(l);
    }
}

__global__ void rope_k() {
    int s = blockIdx.x;
    int idx = threadIdx.x;
    int h = idx >> 5, i = idx & 31;
    float c = g_cos[s * 32 + i], sn = g_sin[s * 32 + i];
    size_t base = (size_t)s * QKVN + h * 64 + 2 * i;
    float q0 = g_qkv[base], q1 = g_qkv[base + 1];
    g_qkv[base]     = q0 * c - q1 * sn;
    g_qkv[base + 1] = q0 * sn + q1 * c;
    float k0 = g_qkv[base + 2048], k1 = g_qkv[base + 2049];
    g_qkv[base + 2048] = k0 * c - k1 * sn;
    g_qkv[base + 2049] = k0 * sn + k1 * c;
}

// ---------------- attention (reference per-block max semantics) ----------------
__global__ void attn_k() {
    int h  = blockIdx.x;
    int ib = blockIdx.y;
    __shared__ float Qs[64 * 64];
    __shared__ float KV[64 * 64];
    __shared__ float SC[64 * 64];
    int tid = threadIdx.x;
    int tx = tid & 15, ty = tid >> 4;

    for (int idx = tid; idx < 1024; idx += 256) {
        int r = idx >> 4, c4 = (idx & 15) * 4;
        *(float4*)&Qs[r * 64 + c4] =
            *(const float4*)&g_qkv[(size_t)(ib * 64 + r) * QKVN + h * 64 + c4];
    }
    float acc[4][4];
    #pragma unroll
    for (int u = 0; u < 4; u++)
        #pragma unroll
        for (int v = 0; v < 4; v++) acc[u][v] = 0.f;
    float Lacc = 0.f;

    for (int j = 0; j <= ib; j++) {
        __syncthreads();
        for (int idx = tid; idx < 1024; idx += 256) {
            int r = idx >> 4, c4 = (idx & 15) * 4;
            float4 kv = *(const float4*)&g_qkv[(size_t)(j * 64 + r) * QKVN + 2048 + h * 64 + c4];
            KV[(c4 + 0) * 64 + r] = kv.x; KV[(c4 + 1) * 64 + r] = kv.y;
            KV[(c4 + 2) * 64 + r] = kv.z; KV[(c4 + 3) * 64 + r] = kv.w;
        }
        __syncthreads();
        {
            float sc[4][4];
            #pragma unroll
            for (int u = 0; u < 4; u++)
                #pragma unroll
                for (int v = 0; v < 4; v++) sc[u][v] = 0.f;
            for (int kk = 0; kk < 64; kk++) {
                float qv[4], kvv[4];
                #pragma unroll
                for (int u = 0; u < 4; u++) qv[u] = Qs[(ty * 4 + u) * 64 + kk];
                #pragma unroll
                for (int v = 0; v < 4; v++) kvv[v] = KV[kk * 64 + tx * 4 + v];
                #pragma unroll
                for (int u = 0; u < 4; u++)
                    #pragma unroll
                    for (int v = 0; v < 4; v++) sc[u][v] += qv[u] * kvv[v];
            }
            #pragma unroll
            for (int u = 0; u < 4; u++)
                #pragma unroll
                for (int v = 0; v < 4; v++)
                    SC[(ty * 4 + u) * 64 + tx * 4 + v] = sc[u][v] * 0.125f;
        }
        __syncthreads();
        if (tid < 64) {
            int r = tid;
            int kmax = (j == ib) ? r : 63;
            float m = -1e30f;
            for (int kk = 0; kk <= kmax; kk++) m = fmaxf(m, SC[r * 64 + kk]);
            float ssum = 0.f;
            for (int kk = 0; kk < 64; kk++) {
                float p = (kk <= kmax) ? __expf(SC[r * 64 + kk] - m) : 0.f;
                SC[r * 64 + kk] = p;
                ssum += p;
            }
            Lacc += ssum;
        }
        __syncthreads();
        for (int idx = tid; idx < 1024; idx += 256) {
            int r = idx >> 4, c4 = (idx & 15) * 4;
            *(float4*)&KV[r * 64 + c4] =
                *(const float4*)&g_qkv[(size_t)(j * 64 + r) * QKVN + 4096 + h * 64 + c4];
        }
        __syncthreads();
        for (int kk = 0; kk < 64; kk++) {
            float pv[4], vv[4];
            #pragma unroll
            for (int u = 0; u < 4; u++) pv[u] = SC[(ty * 4 + u) * 64 + kk];
            #pragma unroll
            for (int v = 0; v < 4; v++) vv[v] = KV[kk * 64 + tx * 4 + v];
            #pragma unroll
            for (int u = 0; u < 4; u++)
                #pragma unroll
                for (int v = 0; v < 4; v++) acc[u][v] += pv[u] * vv[v];
        }
    }
    __syncthreads();
    if (tid < 64) SC[tid] = Lacc;
    __syncthreads();
    #pragma unroll
    for (int u = 0; u < 4; u++) {
        int r = ty * 4 + u;
        float invl = 1.f / (SC[r] + 1e-6f);
        #pragma unroll
        for (int v = 0; v < 4; v++) {
            float val = acc[u][v] * invl;
            size_t o = (size_t)(ib * 64 + r) * DM + h * 64 + tx * 4 + v;
            split2(val, &g_ath[o], &g_atl[o]);
        }
    }
}

// ---------------- layernorm (+ split) ----------------
__global__ void layernorm_k(const float* __restrict__ X, const float* __restrict__ g,
                            const float* __restrict__ b, float* __restrict__ Y,
                            __nv_bfloat16* __restrict__ Yh, __nv_bfloat16* __restrict__ Yl) {
    int t = blockIdx.x;
    __shared__ float sm[8];
    const float* x = X + (size_t)t * DM;
    float loc[8];
    float s = 0.f, ss = 0.f;
    #pragma unroll
    for (int i = 0; i < 8; i++) {
        float v = x[threadIdx.x + i * 256];
        loc[i] = v; s += v; ss += v * v;
    }
    s  = block_sum_256(s, sm);
    ss = block_sum_256(ss, sm);
    float mu  = s * (1.f / DM);
    float var = ss * (1.f / DM) - mu * mu;
    float inv = rsqrtf(var + 1e-5f);
    #pragma unroll
    for (int i = 0; i < 8; i++) {
        int d = threadIdx.x + i * 256;
        float v = (loc[i] - mu) * inv * g[d] + b[d];
        Y[(size_t)t * DM + d] = v;
        split2(v, &Yh[(size_t)t * DM + d], &Yl[(size_t)t * DM + d]);
    }
}

__global__ void init_moe_k() {
    if (threadIdx.x < NE) g_cnt[threadIdx.x] = 0;
    if (threadIdx.x == NE) g_aux = 0.f;
}

__global__ void gate_k(const float* __restrict__ X2, const float* __restrict__ GW) {
    int t = blockIdx.x;
    __shared__ float sm[4][4];
    float p0 = 0.f, p1 = 0.f, p2 = 0.f, p3 = 0.f;
    for (int d = threadIdx.x; d < DM; d += 128) {
        float xv = X2[(size_t)t * DM + d];
        p0 += xv * GW[0 * DM + d]; p1 += xv * GW[1 * DM + d];
        p2 += xv * GW[2 * DM + d]; p3 += xv * GW[3 * DM + d];
    }
    #pragma unroll
    for (int o = 16; o > 0; o >>= 1) {
        p0 += __shfl_down_sync(0xffffffffu, p0, o);
        p1 += __shfl_down_sync(0xffffffffu, p1, o);
        p2 += __shfl_down_sync(0xffffffffu, p2, o);
        p3 += __shfl_down_sync(0xffffffffu, p3, o);
    }
    int w = threadIdx.x >> 5;
    if ((threadIdx.x & 31) == 0) { sm[w][0] = p0; sm[w][1] = p1; sm[w][2] = p2; sm[w][3] = p3; }
    __syncthreads();
    if (threadIdx.x == 0) {
        float l[4];
        #pragma unroll
        for (int e = 0; e < 4; e++) l[e] = sm[0][e] + sm[1][e] + sm[2][e] + sm[3][e];
        float mean = (l[0] + l[1] + l[2] + l[3]) * 0.25f;
        float var = 0.f;
        #pragma unroll
        for (int e = 0; e < 4; e++) var += (l[e] - mean) * (l[e] - mean);
        var *= (1.f / 3.f);
        atomicAdd(&g_aux, var * (1.f / SQ));
        float m = fmaxf(fmaxf(l[0], l[1]), fmaxf(l[2], l[3]));
        float pe[4]; float Z = 0.f;
        #pragma unroll
        for (int e = 0; e < 4; e++) { pe[e] = expf(l[e] - m); Z += pe[e]; }
        #pragma unroll
        for (int e = 0; e < 4; e++) pe[e] /= Z;
        int i1 = 0;
        for (int e = 1; e < 4; e++) if (pe[e] > pe[i1]) i1 = e;
        int i2 = -1;
        for (int e = 0; e < 4; e++) if (e != i1 && (i2 < 0 || pe[e] > pe[i2])) i2 = e;
        float den = pe[i1] + pe[i2];
        int s0 = atomicAdd(&g_cnt[i1], 1);
        g_etok[i1 * SQ + s0] = t;
        g_tok_slot[2 * t] = i1 * SQ + s0;
        g_tok_w[2 * t] = pe[i1] / den;
        int s1 = atomicAdd(&g_cnt[i2], 1);
        g_etok[i2 * SQ + s1] = t;
        g_tok_slot[2 * t + 1] = i2 * SQ + s1;
        g_tok_w[2 * t + 1] = pe[i2] / den;
    }
}

__global__ void combine_ln_k(const float* __restrict__ Y, const float* __restrict__ X2,
                             const float* __restrict__ ln2g, const float* __restrict__ ln2b,
                             const float* __restrict__ fing, const float* __restrict__ finb) {
    int t = blockIdx.x;
    __shared__ float sm[8];
    int f0 = g_tok_slot[t * 2], f1 = g_tok_slot[t * 2 + 1];
    float w0 = g_tok_w[t * 2], w1 = g_tok_w[t * 2 + 1];
    const float* y0 = Y + (size_t)f0 * DM;
    const float* y1 = Y + (size_t)f1 * DM;
    float loc[8];
    float s = 0.f, ss = 0.f;
    #pragma unroll
    for (int i = 0; i < 8; i++) {
        int d = threadIdx.x + i * 256;
        float a = w0 * y0[d] + w1 * y1[d] + X2[(size_t)t * DM + d];
        loc[i] = a; s += a; ss += a * a;
    }
    s  = block_sum_256(s, sm);
    ss = block_sum_256(ss, sm);
    float mu  = s * (1.f / DM);
    float var = ss * (1.f / DM) - mu * mu;
    float inv = rsqrtf(var + 1e-5f);
    float s2 = 0.f, ss2 = 0.f;
    #pragma unroll
    for (int i = 0; i < 8; i++) {
        int d = threadIdx.x + i * 256;
        float bn = (loc[i] - mu) * inv * ln2g[d] + ln2b[d];
        loc[i] = bn; s2 += bn; ss2 += bn * bn;
    }
    s2  = block_sum_256(s2, sm);
    ss2 = block_sum_256(ss2, sm);
    float mu2  = s2 * (1.f / DM);
    float var2 = ss2 * (1.f / DM) - mu2 * mu2;
    float inv2 = rsqrtf(var2 + 1e-5f);
    #pragma unroll
    for (int i = 0; i < 8; i++) {
        int d = threadIdx.x + i * 256;
        float v = (loc[i] - mu2) * inv2 * fing[d] + finb[d];
        split2(v, &g_x3h[(size_t)t * DM + d], &g_x3l[(size_t)t * DM + d]);
    }
}

__global__ void aux_write_k(float* out, int out_size) {
    if (out_size > SQ * VOC) out[(size_t)SQ * VOC] = g_aux;
}

// ---------------- launch ----------------
extern "C" void kernel_launch(void* const* d_in, const int* in_sizes, int n_in,
                              void* d_out, int out_size) {
    const int*   tokens = (const int*)d_in[0];
    const float* emb    = (const float*)d_in[1];
    const float* wq     = (const float*)d_in[2];
    const float* wk     = (const float*)d_in[3];
    const float* wv     = (const float*)d_in[4];
    const float* wo     = (const float*)d_in[5];
    const float* ln1_g  = (const float*)d_in[6];
    const float* ln1_b  = (const float*)d_in[7];
    const float* gate_w = (const float*)d_in[8];
    const float* w1     = (const float*)d_in[9];
    const float* w2     = (const float*)d_in[10];
    const float* w3     = (const float*)d_in[11];
    const float* ln2_g  = (const float*)d_in[12];
    const float* ln2_b  = (const float*)d_in[13];
    const float* fin_g  = (const float*)d_in[14];
    const float* fin_b  = (const float*)d_in[15];
    const float* head_w = (const float*)d_in[16];
    float* out = (float*)d_out;

    cudaFuncSetAttribute(mma_gemm, cudaFuncAttributeMaxDynamicSharedMemorySize, GSMEM_BYTES);

    float *p_x, *p_qkv, *p_x1, *p_x2, *p_h1, *p_y;
    __nv_bfloat16 *p_xh, *p_xl, *p_ath, *p_atl, *p_x2h, *p_x2l, *p_x3h, *p_x3l, *p_hh, *p_hl;
    int *p_etok;
    cudaGetSymbolAddress((void**)&p_x, g_x);     cudaGetSymbolAddress((void**)&p_qkv, g_qkv);
    cudaGetSymbolAddress((void**)&p_x1, g_x1);   cudaGetSymbolAddress((void**)&p_x2, g_x2);
    cudaGetSymbolAddress((void**)&p_h1, g_h1);   cudaGetSymbolAddress((void**)&p_y, g_y);
    cudaGetSymbolAddress((void**)&p_xh, g_xh);   cudaGetSymbolAddress((void**)&p_xl, g_xl);
    cudaGetSymbolAddress((void**)&p_ath, g_ath); cudaGetSymbolAddress((void**)&p_atl, g_atl);
    cudaGetSymbolAddress((void**)&p_x2h, g_x2h); cudaGetSymbolAddress((void**)&p_x2l, g_x2l);
    cudaGetSymbolAddress((void**)&p_x3h, g_x3h); cudaGetSymbolAddress((void**)&p_x3l, g_x3l);
    cudaGetSymbolAddress((void**)&p_hh, g_hh);   cudaGetSymbolAddress((void**)&p_hl, g_hl);
    cudaGetSymbolAddress((void**)&p_etok, g_etok);

    // launch order: #4 (= ncu-profiled slot) is the Q-projection mma_gemm
    embed_k<<<SQ, 256>>>(tokens, emb);
    ropetab_k<<<SQ, 32>>>();
    init_moe_k<<<1, 32>>>();

    // QKV projections: C columns packed into g_qkv (ldc = QKVN)
    mma_gemm<<<dim3(8, DM/128, 1), 256, GSMEM_BYTES>>>(p_xh, p_xl, wq,
        p_qkv,        nullptr, nullptr, nullptr, nullptr, nullptr, SQ, DM, DM, QKVN, 0, 0, 0);
    mma_gemm<<<dim3(8, DM/128, 1), 256, GSMEM_BYTES>>>(p_xh, p_xl, wk,
        p_qkv + 2048, nullptr, nullptr, nullptr, nullptr, nullptr, SQ, DM, DM, QKVN, 0, 0, 0);
    mma_gemm<<<dim3(8, DM/128, 1), 256, GSMEM_BYTES>>>(p_xh, p_xl, wv,
        p_qkv + 4096, nullptr, nullptr, nullptr, nullptr, nullptr, SQ, DM, DM, QKVN, 0, 0, 0);

    rope_k<<<SQ, 1024>>>();
    attn_k<<<dim3(NH, NBLK), 256>>>();

    // O-proj + residual
    mma_gemm<<<dim3(8, DM/128, 1), 256, GSMEM_BYTES>>>(p_ath, p_atl, wo,
        p_x1, p_x, nullptr, nullptr, nullptr, nullptr, SQ, DM, DM, DM, 0, 0, 0);
    layernorm_k<<<SQ, 256>>>(p_x1, ln1_g, ln1_b, p_x2, p_x2h, p_x2l);

    gate_k<<<SQ, 128>>>(p_x2, gate_w);

    // MoE: w1 -> h1 fp32, w3 with fused silu -> split h
    mma_gemm<<<dim3(8, DF/128, NE), 256, GSMEM_BYTES>>>(p_x2h, p_x2l, w1,
        p_h1, nullptr, nullptr, nullptr, nullptr, p_etok, -1, DF, DM, DF, 0, (long)DF*DM, (long)SQ*DF);
    mma_gemm<<<dim3(8, DF/128, NE), 256, GSMEM_BYTES>>>(p_x2h, p_x2l, w3,
        nullptr, nullptr, p_h1, p_hh, p_hl, p_etok, -1, DF, DM, DF, 0, (long)DF*DM, (long)SQ*DF);
    mma_gemm<<<dim3(8, DM/128, NE), 256, GSMEM_BYTES>>>(p_hh, p_hl, w2,
        p_y, nullptr, nullptr, nullptr, nullptr, nullptr, -1, DM, DF, DM, (long)SQ*DF, (long)DM*DF, (long)SQ*DM);

    combine_ln_k<<<SQ, 256>>>(p_y, p_x2, ln2_g, ln2_b, fin_g, fin_b);

    // head
    mma_gemm<<<dim3(8, (VOC + 127)/128, 1), 256, GSMEM_BYTES>>>(p_x3h, p_x3l, head_w,
        out, nullptr, nullptr, nullptr, nullptr, nullptr, SQ, VOC, DM, VOC, 0, 0, 0);
    aux_write_k<<<1, 1>>>(out, out_size);
}

// round 17
// speedup vs baseline: 1.6207x; 1.6207x over previous
#include <cuda_runtime.h>
#include <cuda_bf16.h>
#include <cuda_fp16.h>
#include <math.h>
#include <stdint.h>

#define SQ   1024
#define DM   2048
#define NH   32
#define NBLK 16
#define NE   4
#define DF   8192
#define VOC  50257
#define QKVN 6144

// ---------------- scratch ----------------
__device__ float g_x  [SQ*DM];
__device__ float g_qkv[SQ*QKVN];
__device__ float g_x1 [SQ*DM];
__device__ float g_x2 [SQ*DM];
__device__ float g_cos[SQ*32];
__device__ float g_sin[SQ*32];
__device__ int   g_cnt[NE];
__device__ int   g_etok[NE*SQ];
__device__ int   g_tok_slot[SQ*2];
__device__ float g_tok_w  [SQ*2];
__device__ float g_h1[NE*SQ*DF];
__device__ float g_y [NE*SQ*DM];
__device__ float g_aux;

__device__ __align__(16) __nv_bfloat16 g_xh [SQ*DM],  g_xl [SQ*DM];
__device__ __align__(16) __nv_bfloat16 g_ath[SQ*DM],  g_atl[SQ*DM];
__device__ __align__(16) __nv_bfloat16 g_x2h[SQ*DM],  g_x2l[SQ*DM];
__device__ __align__(16) __half        g_x3f[SQ*DM];
__device__ __align__(16) __nv_bfloat16 g_hh [NE*SQ*DF], g_hl[NE*SQ*DF];
__device__ __align__(16) __nv_bfloat16 g_wqkvh[3*DM*DM], g_wqkvl[3*DM*DM];
__device__ __align__(16) __nv_bfloat16 g_woh [DM*DM],    g_wol [DM*DM];
__device__ __align__(16) __nv_bfloat16 g_w1h [NE*DF*DM], g_w1l [NE*DF*DM];
__device__ __align__(16) __nv_bfloat16 g_w3h [NE*DF*DM], g_w3l [NE*DF*DM];
__device__ __align__(16) __nv_bfloat16 g_w2h [NE*DM*DF], g_w2l [NE*DM*DF];
__device__ __align__(16) __half        g_hwf [VOC*DM];

// ---------------- helpers ----------------
__device__ __forceinline__ uint32_t s2u(const void* p) {
    uint32_t a;
    asm("{ .reg .u64 t; cvta.to.shared.u64 t, %1; cvt.u32.u64 %0, t; }" : "=r"(a) : "l"(p));
    return a;
}
__device__ __forceinline__ void cpa16(uint32_t dst, const void* src, int sz) {
    asm volatile("cp.async.cg.shared.global [%0], [%1], 16, %2;" :: "r"(dst), "l"(src), "r"(sz) : "memory");
}
#define CPA_COMMIT() asm volatile("cp.async.commit_group;" ::: "memory")

__device__ __forceinline__ void ldsm4(uint32_t* r, uint32_t addr) {
    asm volatile("ldmatrix.sync.aligned.m8n8.x4.shared.b16 {%0,%1,%2,%3}, [%4];"
        : "=r"(r[0]), "=r"(r[1]), "=r"(r[2]), "=r"(r[3]) : "r"(addr));
}
__device__ __forceinline__ void mma16816(float* d, const uint32_t* a, const uint32_t* b) {
    asm volatile("mma.sync.aligned.m16n8k16.row.col.f32.bf16.bf16.f32 "
        "{%0,%1,%2,%3}, {%4,%5,%6,%7}, {%8,%9}, {%0,%1,%2,%3};"
        : "+f"(d[0]), "+f"(d[1]), "+f"(d[2]), "+f"(d[3])
        : "r"(a[0]), "r"(a[1]), "r"(a[2]), "r"(a[3]), "r"(b[0]), "r"(b[1]));
}
__device__ __forceinline__ void mma16816h(float* d, const uint32_t* a, const uint32_t* b) {
    asm volatile("mma.sync.aligned.m16n8k16.row.col.f32.f16.f16.f32 "
        "{%0,%1,%2,%3}, {%4,%5,%6,%7}, {%8,%9}, {%0,%1,%2,%3};"
        : "+f"(d[0]), "+f"(d[1]), "+f"(d[2]), "+f"(d[3])
        : "r"(a[0]), "r"(a[1]), "r"(a[2]), "r"(a[3]), "r"(b[0]), "r"(b[1]));
}
__device__ __forceinline__ void split2(float v, __nv_bfloat16* h, __nv_bfloat16* l) {
    __nv_bfloat16 hh = __float2bfloat16(v);
    *h = hh;
    *l = __float2bfloat16(v - __bfloat162float(hh));
}
__device__ __forceinline__ float block_sum_256(float v, float* sm) {
    __syncthreads();
    #pragma unroll
    for (int o = 16; o > 0; o >>= 1) v += __shfl_down_sync(0xffffffffu, v, o);
    if ((threadIdx.x & 31) == 0) sm[threadIdx.x >> 5] = v;
    __syncthreads();
    float r = 0.f;
    if (threadIdx.x < 8) {
        r = sm[threadIdx.x];
        #pragma unroll
        for (int o = 4; o > 0; o >>= 1) r += __shfl_down_sync(0x000000ffu, r, o);
        if (threadIdx.x == 0) sm[0] = r;
    }
    __syncthreads();
    return sm[0];
}

// ---------------- mma.sync bf16x3 GEMM (R8 structure): C[m][n] = sum_k A[m][k]*B[n][k] ----------------
// CTA tile 128x128, K-chunk 64, 3-stage cp.async, 8 warps (4M x 2N), warp 32x64.
#define GSMEM_BYTES (3*65536 + 1024)

#define ISSUE_CHUNK(KT, BUF) do {                                              \
    uint32_t bb_ = base + (uint32_t)(BUF) * 65536u;                            \
    long k0_ = (long)(KT) * 64;                                                \
    _Pragma("unroll")                                                          \
    for (int u = tid; u < 1024; u += 256) {                                    \
        int r_ = u >> 3, kc_ = u & 7;                                          \
        uint32_t smo_ = (uint32_t)(r_ * 128 + ((kc_ ^ (r_ & 7)) << 4));        \
        int rv_ = rowsm[r_];                                                   \
        int okA_ = (rv_ >= 0) ? 16 : 0;                                        \
        long ga_ = ((rv_ >= 0) ? (long)rv_ : 0) * (long)K + k0_ + kc_ * 8;     \
        cpa16(bb_ + smo_,          Ah + ga_, okA_);                            \
        cpa16(bb_ + 16384 + smo_,  Al + ga_, okA_);                            \
        int nn_ = n0 + r_;                                                     \
        int okB_ = (nn_ < N) ? 16 : 0;                                         \
        long gb_ = ((nn_ < N) ? (long)nn_ : 0) * (long)K + k0_ + kc_ * 8;      \
        cpa16(bb_ + 32768 + smo_,  Bh + gb_, okB_);                            \
        cpa16(bb_ + 49152 + smo_,  Bl + gb_, okB_);                            \
    }                                                                          \
    CPA_COMMIT();                                                              \
} while (0)

__global__ __launch_bounds__(256, 1)
void mma_gemm(const __nv_bfloat16* __restrict__ Ah, const __nv_bfloat16* __restrict__ Al,
              const __nv_bfloat16* __restrict__ Bh, const __nv_bfloat16* __restrict__ Bl,
              float* __restrict__ C, const float* __restrict__ Res,
              const float* __restrict__ H1,
              __nv_bfloat16* __restrict__ Ch, __nv_bfloat16* __restrict__ Cl,
              const int* __restrict__ gatherB,
              int M, int N, int K, int ldc,
              long aStrE, long bStrE, long cStrE)
{
    extern __shared__ char dsm[];
    __shared__ int rowsm[128];

    int e = blockIdx.z;
    if (M < 0) M = g_cnt[e];
    int m0 = blockIdx.x * 128;
    if (m0 >= M) return;
    int n0 = blockIdx.y * 128;
    Ah += (long)e * aStrE; Al += (long)e * aStrE;
    Bh += (long)e * bStrE; Bl += (long)e * bStrE;
    C  += (long)e * cStrE;
    if (H1) { H1 += (long)e * cStrE; Ch += (long)e * cStrE; Cl += (long)e * cStrE; }
    const int* gth = gatherB ? (gatherB + e * SQ) : nullptr;

    int tid = threadIdx.x, wid = tid >> 5, lane = tid & 31;
    if (tid < 128) {
        int m = m0 + tid;
        rowsm[tid] = (m < M) ? (gth ? gth[m] : m) : -1;
    }
    __syncthreads();

    uint32_t base = (s2u(dsm) + 1023u) & ~1023u;
    int m0w = (wid >> 1) * 32;
    int n0w = (wid & 1) * 64;
    int tq = lane >> 3, li = lane & 7;
    int rA0 = m0w + (tq & 1) * 8 + li;
    int rB0 = n0w + (tq >> 1) * 8 + li;
    int kuA = tq >> 1;
    int kuB = tq & 1;

    float acc[2][8][4];
    #pragma unroll
    for (int mt = 0; mt < 2; mt++)
        #pragma unroll
        for (int nt = 0; nt < 8; nt++)
            #pragma unroll
            for (int c = 0; c < 4; c++) acc[mt][nt][c] = 0.f;

    int nk = K >> 6;
    ISSUE_CHUNK(0, 0);
    if (nk > 1) ISSUE_CHUNK(1, 1);

    for (int kt = 0; kt < nk; kt++) {
        if (kt + 2 < nk) {
            ISSUE_CHUNK(kt + 2, (kt + 2) % 3);
            asm volatile("cp.async.wait_group 2;" ::: "memory");
        } else if (kt + 1 < nk) {
            asm volatile("cp.async.wait_group 1;" ::: "memory");
        } else {
            asm volatile("cp.async.wait_group 0;" ::: "memory");
        }
        __syncthreads();

        uint32_t bb = base + (uint32_t)(kt % 3) * 65536u;
        #pragma unroll
        for (int ks = 0; ks < 4; ks++) {
            uint32_t ahf[2][4], alf[2][4];
            #pragma unroll
            for (int mt = 0; mt < 2; mt++) {
                int row = rA0 + mt * 16;
                uint32_t ad = bb + (uint32_t)(row * 128 + (((kuA + ks * 2) ^ (row & 7)) << 4));
                ldsm4(ahf[mt], ad);
                ldsm4(alf[mt], ad + 16384);
            }
            uint32_t bhf[4][4], blf[4][4];
            #pragma unroll
            for (int g = 0; g < 4; g++) {
                int row = rB0 + g * 16;
                uint32_t bd = bb + 32768 + (uint32_t)(row * 128 + (((kuB + ks * 2) ^ (row & 7)) << 4));
                ldsm4(bhf[g], bd);
                ldsm4(blf[g], bd + 16384);
            }
            #pragma unroll
            for (int mt = 0; mt < 2; mt++)
                #pragma unroll
                for (int g = 0; g < 4; g++)
                    #pragma unroll
                    for (int hh = 0; hh < 2; hh++) {
                        float* d = acc[mt][g * 2 + hh];
                        mma16816(d, ahf[mt], &bhf[g][hh * 2]);
                        mma16816(d, ahf[mt], &blf[g][hh * 2]);
                        mma16816(d, alf[mt], &bhf[g][hh * 2]);
                    }
        }
        __syncthreads();
    }

    // epilogue
    #pragma unroll
    for (int mt = 0; mt < 2; mt++) {
        #pragma unroll
        for (int half = 0; half < 2; half++) {
            int row = m0 + m0w + mt * 16 + (lane >> 2) + half * 8;
            if (row >= M) continue;
            long o = (long)row * ldc;
            #pragma unroll
            for (int nt = 0; nt < 8; nt++) {
                int col = n0 + n0w + nt * 8 + (lane & 3) * 2;
                float d0 = acc[mt][nt][half * 2], d1 = acc[mt][nt][half * 2 + 1];
                if (H1) {   // fused silu(h1)*acc -> bf16 split
                    if (col < N) {
                        float hv = H1[o + col];
                        float v = hv / (1.f + __expf(-hv)) * d0;
                        split2(v, &Ch[o + col], &Cl[o + col]);
                    }
                    if (col + 1 < N) {
                        float hv = H1[o + col + 1];
                        float v = hv / (1.f + __expf(-hv)) * d1;
                        split2(v, &Ch[o + col + 1], &Cl[o + col + 1]);
                    }
                } else if (Res) {
                    if (col < N)     C[o + col]     = d0 + Res[o + col];
                    if (col + 1 < N) C[o + col + 1] = d1 + Res[o + col + 1];
                } else {
                    if (col < N)     C[o + col]     = d0;
                    if (col + 1 < N) C[o + col + 1] = d1;
                }
            }
        }
    }
}

// ---------------- fp16 single-MMA GEMM (terminal head GEMM only) ----------------
// CTA tile 128x128, K-chunk 64, 3-stage, 32KB/stage -> 2 CTAs/SM.
#define FSMEM_BYTES (3*32768 + 1024)

#define ISSUE_F16(KT, BUF) do {                                                \
    uint32_t bb_ = fbase + (uint32_t)(BUF) * 32768u;                           \
    long k0_ = (long)(KT) * 64;                                                \
    _Pragma("unroll")                                                          \
    for (int u = tid; u < 2048; u += 256) {                                    \
        int r_ = (u & 1023) >> 3, kc_ = u & 7;                                 \
        uint32_t smo_ = (uint32_t)(r_ * 128 + ((kc_ ^ (r_ & 7)) << 4));        \
        if (u < 1024) {                                                        \
            int mm_ = m0 + r_;                                                 \
            int ok_ = (mm_ < M) ? 16 : 0;                                      \
            cpa16(bb_ + smo_, A + ((mm_ < M) ? (long)mm_ : 0) * K + k0_ + kc_ * 8, ok_); \
        } else {                                                               \
            int nn_ = n0 + r_;                                                 \
            int ok_ = (nn_ < N) ? 16 : 0;                                      \
            cpa16(bb_ + 16384 + smo_, B + ((nn_ < N) ? (long)nn_ : 0) * K + k0_ + kc_ * 8, ok_); \
        }                                                                      \
    }                                                                          \
    CPA_COMMIT();                                                              \
} while (0)

__global__ __launch_bounds__(256, 2)
void mma_gemm_f16(const __half* __restrict__ A, const __half* __restrict__ B,
                  float* __restrict__ C, int M, int N, int K, int ldc)
{
    extern __shared__ char dsm[];
    int m0 = blockIdx.x * 128;
    int n0 = blockIdx.y * 128;
    int tid = threadIdx.x, wid = tid >> 5, lane = tid & 31;

    uint32_t fbase = (s2u(dsm) + 1023u) & ~1023u;
    int m0w = (wid >> 1) * 32;
    int n0w = (wid & 1) * 64;
    int tq = lane >> 3, li = lane & 7;
    int rA0 = m0w + (tq & 1) * 8 + li;
    int rB0 = n0w + (tq >> 1) * 8 + li;
    int kuA = tq >> 1;
    int kuB = tq & 1;

    float acc[2][8][4];
    #pragma unroll
    for (int mt = 0; mt < 2; mt++)
        #pragma unroll
        for (int nt = 0; nt < 8; nt++)
            #pragma unroll
            for (int c = 0; c < 4; c++) acc[mt][nt][c] = 0.f;

    int nk = K >> 6;
    ISSUE_F16(0, 0);
    if (nk > 1) ISSUE_F16(1, 1);

    for (int kt = 0; kt < nk; kt++) {
        if (kt + 2 < nk) {
            ISSUE_F16(kt + 2, (kt + 2) % 3);
            asm volatile("cp.async.wait_group 2;" ::: "memory");
        } else if (kt + 1 < nk) {
            asm volatile("cp.async.wait_group 1;" ::: "memory");
        } else {
            asm volatile("cp.async.wait_group 0;" ::: "memory");
        }
        __syncthreads();

        uint32_t bb = fbase + (uint32_t)(kt % 3) * 32768u;
        #pragma unroll
        for (int ks = 0; ks < 4; ks++) {
            uint32_t af[2][4];
            #pragma unroll
            for (int mt = 0; mt < 2; mt++) {
                int row = rA0 + mt * 16;
                ldsm4(af[mt], bb + (uint32_t)(row * 128 + (((kuA + ks * 2) ^ (row & 7)) << 4)));
            }
            uint32_t bf[4][4];
            #pragma unroll
            for (int g = 0; g < 4; g++) {
                int row = rB0 + g * 16;
                ldsm4(bf[g], bb + 16384 + (uint32_t)(row * 128 + (((kuB + ks * 2) ^ (row & 7)) << 4)));
            }
            #pragma unroll
            for (int mt = 0; mt < 2; mt++)
                #pragma unroll
                for (int g = 0; g < 4; g++)
                    #pragma unroll
                    for (int hh = 0; hh < 2; hh++)
                        mma16816h(acc[mt][g * 2 + hh], af[mt], &bf[g][hh * 2]);
        }
        __syncthreads();
    }

    #pragma unroll
    for (int mt = 0; mt < 2; mt++) {
        #pragma unroll
        for (int half = 0; half < 2; half++) {
            int row = m0 + m0w + mt * 16 + (lane >> 2) + half * 8;
            if (row >= M) continue;
            long o = (long)row * ldc;
            #pragma unroll
            for (int nt = 0; nt < 8; nt++) {
                int col = n0 + n0w + nt * 8 + (lane & 3) * 2;
                if (col < N)     C[o + col]     = acc[mt][nt][half * 2];
                if (col + 1 < N) C[o + col + 1] = acc[mt][nt][half * 2 + 1];
            }
        }
    }
}

// ---------------- fp32 -> bf16 hi/lo split ----------------
__global__ void cvt_split_k(const float4* __restrict__ src, uint4* __restrict__ hi,
                            uint4* __restrict__ lo, long n8) {
    long i = (long)blockIdx.x * blockDim.x + threadIdx.x;
    long stride = (long)gridDim.x * blockDim.x;
    for (; i < n8; i += stride) {
        float4 v0 = __ldg(src + 2 * i);
        float4 v1 = __ldg(src + 2 * i + 1);
        __align__(16) __nv_bfloat16 h[8], l[8];
        split2(v0.x, &h[0], &l[0]); split2(v0.y, &h[1], &l[1]);
        split2(v0.z, &h[2], &l[2]); split2(v0.w, &h[3], &l[3]);
        split2(v1.x, &h[4], &l[4]); split2(v1.y, &h[5], &l[5]);
        split2(v1.z, &h[6], &l[6]); split2(v1.w, &h[7], &l[7]);
        hi[i] = *reinterpret_cast<uint4*>(h);
        lo[i] = *reinterpret_cast<uint4*>(l);
    }
}

// ---------------- fp32 -> fp16 ----------------
__global__ void cvt_f16_k(const float4* __restrict__ src, uint4* __restrict__ dst, long n8) {
    long i = (long)blockIdx.x * blockDim.x + threadIdx.x;
    long stride = (long)gridDim.x * blockDim.x;
    for (; i < n8; i += stride) {
        float4 v0 = __ldg(src + 2 * i);
        float4 v1 = __ldg(src + 2 * i + 1);
        __align__(16) __half h[8];
        h[0] = __float2half_rn(v0.x); h[1] = __float2half_rn(v0.y);
        h[2] = __float2half_rn(v0.z); h[3] = __float2half_rn(v0.w);
        h[4] = __float2half_rn(v1.x); h[5] = __float2half_rn(v1.y);
        h[6] = __float2half_rn(v1.z); h[7] = __float2half_rn(v1.w);
        dst[i] = *reinterpret_cast<uint4*>(h);
    }
}

__global__ void ropetab_k() {
    int s = blockIdx.x, i = threadIdx.x;
    double inv = exp(-((double)(2 * i) / 64.0) * log(10000.0));
    double ang = (double)s * inv;
    g_cos[s * 32 + i] = (float)cos(ang);
    g_sin[s * 32 + i] = (float)sin(ang);
}

__global__ void embed_k(const int* __restrict__ tok, const float* __restrict__ emb) {
    int t = blockIdx.x;
    int row = tok[t];
    const float4* src = (const float4*)(emb + (size_t)row * DM);
    for (int i = threadIdx.x; i < DM / 4; i += blockDim.x) {
        float4 v = src[i];
        *(float4*)(g_x + (size_t)t * DM + 4 * i) = v;
        __align__(8) __nv_bfloat16 h[4], l[4];
        split2(v.x, &h[0], &l[0]); split2(v.y, &h[1], &l[1]);
        split2(v.z, &h[2], &l[2]); split2(v.w, &h[3], &l[3]);
        *reinterpret_cast<uint2*>(g_xh + (size_t)t * DM + 4 * i) = *reinterpret_cast<uint2*>(h);
        *reinterpret_cast<uint2*>(g_xl + (size_t)t * DM + 4 * i) = *reinterpret_cast<uint2*>(l);
    }
}

__global__ void rope_k() {
    int s = blockIdx.x;
    int idx = threadIdx.x;
    int h = idx >> 5, i = idx & 31;
    float c = g_cos[s * 32 + i], sn = g_sin[s * 32 + i];
    size_t base = (size_t)s * QKVN + h * 64 + 2 * i;
    float q0 = g_qkv[base], q1 = g_qkv[base + 1];
    g_qkv[base]     = q0 * c - q1 * sn;
    g_qkv[base + 1] = q0 * sn + q1 * c;
    float k0 = g_qkv[base + 2048], k1 = g_qkv[base + 2049];
    g_qkv[base + 2048] = k0 * c - k1 * sn;
    g_qkv[base + 2049] = k0 * sn + k1 * c;
}

// ---------------- attention (reference per-block max semantics) ----------------
__global__ void attn_k() {
    int h  = blockIdx.x;
    int ib = blockIdx.y;
    __shared__ float Qs[64 * 64];
    __shared__ float KV[64 * 64];
    __shared__ float SC[64 * 64];
    int tid = threadIdx.x;
    int tx = tid & 15, ty = tid >> 4;

    for (int idx = tid; idx < 1024; idx += 256) {
        int r = idx >> 4, c4 = (idx & 15) * 4;
        *(float4*)&Qs[r * 64 + c4] =
            *(const float4*)&g_qkv[(size_t)(ib * 64 + r) * QKVN + h * 64 + c4];
    }
    float acc[4][4];
    #pragma unroll
    for (int u = 0; u < 4; u++)
        #pragma unroll
        for (int v = 0; v < 4; v++) acc[u][v] = 0.f;
    float Lacc = 0.f;

    for (int j = 0; j <= ib; j++) {
        __syncthreads();
        for (int idx = tid; idx < 1024; idx += 256) {
            int r = idx >> 4, c4 = (idx & 15) * 4;
            float4 kv = *(const float4*)&g_qkv[(size_t)(j * 64 + r) * QKVN + 2048 + h * 64 + c4];
            KV[(c4 + 0) * 64 + r] = kv.x; KV[(c4 + 1) * 64 + r] = kv.y;
            KV[(c4 + 2) * 64 + r] = kv.z; KV[(c4 + 3) * 64 + r] = kv.w;
        }
        __syncthreads();
        {
            float sc[4][4];
            #pragma unroll
            for (int u = 0; u < 4; u++)
                #pragma unroll
                for (int v = 0; v < 4; v++) sc[u][v] = 0.f;
            for (int kk = 0; kk < 64; kk++) {
                float qv[4], kvv[4];
                #pragma unroll
                for (int u = 0; u < 4; u++) qv[u] = Qs[(ty * 4 + u) * 64 + kk];
                #pragma unroll
                for (int v = 0; v < 4; v++) kvv[v] = KV[kk * 64 + tx * 4 + v];
                #pragma unroll
                for (int u = 0; u < 4; u++)
                    #pragma unroll
                    for (int v = 0; v < 4; v++) sc[u][v] += qv[u] * kvv[v];
            }
            #pragma unroll
            for (int u = 0; u < 4; u++)
                #pragma unroll
                for (int v = 0; v < 4; v++)
                    SC[(ty * 4 + u) * 64 + tx * 4 + v] = sc[u][v] * 0.125f;
        }
        __syncthreads();
        if (tid < 64) {
            int r = tid;
            int kmax = (j == ib) ? r : 63;
            float m = -1e30f;
            for (int kk = 0; kk <= kmax; kk++) m = fmaxf(m, SC[r * 64 + kk]);
            float ssum = 0.f;
            for (int kk = 0; kk < 64; kk++) {
                float p = (kk <= kmax) ? __expf(SC[r * 64 + kk] - m) : 0.f;
                SC[r * 64 + kk] = p;
                ssum += p;
            }
            Lacc += ssum;
        }
        __syncthreads();
        for (int idx = tid; idx < 1024; idx += 256) {
            int r = idx >> 4, c4 = (idx & 15) * 4;
            *(float4*)&KV[r * 64 + c4] =
                *(const float4*)&g_qkv[(size_t)(j * 64 + r) * QKVN + 4096 + h * 64 + c4];
        }
        __syncthreads();
        for (int kk = 0; kk < 64; kk++) {
            float pv[4], vv[4];
            #pragma unroll
            for (int u = 0; u < 4; u++) pv[u] = SC[(ty * 4 + u) * 64 + kk];
            #pragma unroll
            for (int v = 0; v < 4; v++) vv[v] = KV[kk * 64 + tx * 4 + v];
            #pragma unroll
            for (int u = 0; u < 4; u++)
                #pragma unroll
                for (int v = 0; v < 4; v++) acc[u][v] += pv[u] * vv[v];
        }
    }
    __syncthreads();
    if (tid < 64) SC[tid] = Lacc;
    __syncthreads();
    #pragma unroll
    for (int u = 0; u < 4; u++) {
        int r = ty * 4 + u;
        float invl = 1.f / (SC[r] + 1e-6f);
        #pragma unroll
        for (int v = 0; v < 4; v++) {
            float val = acc[u][v] * invl;
            size_t o = (size_t)(ib * 64 + r) * DM + h * 64 + tx * 4 + v;
            split2(val, &g_ath[o], &g_atl[o]);
        }
    }
}

// ---------------- layernorm (+ split) ----------------
__global__ void layernorm_k(const float* __restrict__ X, const float* __restrict__ g,
                            const float* __restrict__ b, float* __restrict__ Y,
                            __nv_bfloat16* __restrict__ Yh, __nv_bfloat16* __restrict__ Yl) {
    int t = blockIdx.x;
    __shared__ float sm[8];
    const float* x = X + (size_t)t * DM;
    float loc[8];
    float s = 0.f, ss = 0.f;
    #pragma unroll
    for (int i = 0; i < 8; i++) {
        float v = x[threadIdx.x + i * 256];
        loc[i] = v; s += v; ss += v * v;
    }
    s  = block_sum_256(s, sm);
    ss = block_sum_256(ss, sm);
    float mu  = s * (1.f / DM);
    float var = ss * (1.f / DM) - mu * mu;
    float inv = rsqrtf(var + 1e-5f);
    #pragma unroll
    for (int i = 0; i < 8; i++) {
        int d = threadIdx.x + i * 256;
        float v = (loc[i] - mu) * inv * g[d] + b[d];
        Y[(size_t)t * DM + d] = v;
        split2(v, &Yh[(size_t)t * DM + d], &Yl[(size_t)t * DM + d]);
    }
}

__global__ void init_moe_k() {
    if (threadIdx.x < NE) g_cnt[threadIdx.x] = 0;
    if (threadIdx.x == NE) g_aux = 0.f;
}

__global__ void gate_k(const float* __restrict__ X2, const float* __restrict__ GW) {
    int t = blockIdx.x;
    __shared__ float sm[4][4];
    float p0 = 0.f, p1 = 0.f, p2 = 0.f, p3 = 0.f;
    for (int d = threadIdx.x; d < DM; d += 128) {
        float xv = X2[(size_t)t * DM + d];
        p0 += xv * GW[0 * DM + d]; p1 += xv * GW[1 * DM + d];
        p2 += xv * GW[2 * DM + d]; p3 += xv * GW[3 * DM + d];
    }
    #pragma unroll
    for (int o = 16; o > 0; o >>= 1) {
        p0 += __shfl_down_sync(0xffffffffu, p0, o);
        p1 += __shfl_down_sync(0xffffffffu, p1, o);
        p2 += __shfl_down_sync(0xffffffffu, p2, o);
        p3 += __shfl_down_sync(0xffffffffu, p3, o);
    }
    int w = threadIdx.x >> 5;
    if ((threadIdx.x & 31) == 0) { sm[w][0] = p0; sm[w][1] = p1; sm[w][2] = p2; sm[w][3] = p3; }
    __syncthreads();
    if (threadIdx.x == 0) {
        float l[4];
        #pragma unroll
        for (int e = 0; e < 4; e++) l[e] = sm[0][e] + sm[1][e] + sm[2][e] + sm[3][e];
        float mean = (l[0] + l[1] + l[2] + l[3]) * 0.25f;
        float var = 0.f;
        #pragma unroll
        for (int e = 0; e < 4; e++) var += (l[e] - mean) * (l[e] - mean);
        var *= (1.f / 3.f);
        atomicAdd(&g_aux, var * (1.f / SQ));
        float m = fmaxf(fmaxf(l[0], l[1]), fmaxf(l[2], l[3]));
        float pe[4]; float Z = 0.f;
        #pragma unroll
        for (int e = 0; e < 4; e++) { pe[e] = expf(l[e] - m); Z += pe[e]; }
        #pragma unroll
        for (int e = 0; e < 4; e++) pe[e] /= Z;
        int i1 = 0;
        for (int e = 1; e < 4; e++) if (pe[e] > pe[i1]) i1 = e;
        int i2 = -1;
        for (int e = 0; e < 4; e++) if (e != i1 && (i2 < 0 || pe[e] > pe[i2])) i2 = e;
        float den = pe[i1] + pe[i2];
        int s0 = atomicAdd(&g_cnt[i1], 1);
        g_etok[i1 * SQ + s0] = t;
        g_tok_slot[2 * t] = i1 * SQ + s0;
        g_tok_w[2 * t] = pe[i1] / den;
        int s1 = atomicAdd(&g_cnt[i2], 1);
        g_etok[i2 * SQ + s1] = t;
        g_tok_slot[2 * t + 1] = i2 * SQ + s1;
        g_tok_w[2 * t + 1] = pe[i2] / den;
    }
}

__global__ void combine_ln_k(const float* __restrict__ Y, const float* __restrict__ X2,
                             const float* __restrict__ ln2g, const float* __restrict__ ln2b,
                             const float* __restrict__ fing, const float* __restrict__ finb) {
    int t = blockIdx.x;
    __shared__ float sm[8];
    int f0 = g_tok_slot[t * 2], f1 = g_tok_slot[t * 2 + 1];
    float w0 = g_tok_w[t * 2], w1 = g_tok_w[t * 2 + 1];
    const float* y0 = Y + (size_t)f0 * DM;
    const float* y1 = Y + (size_t)f1 * DM;
    float loc[8];
    float s = 0.f, ss = 0.f;
    #pragma unroll
    for (int i = 0; i < 8; i++) {
        int d = threadIdx.x + i * 256;
        float a = w0 * y0[d] + w1 * y1[d] + X2[(size_t)t * DM + d];
        loc[i] = a; s += a; ss += a * a;
    }
    s  = block_sum_256(s, sm);
    ss = block_sum_256(ss, sm);
    float mu  = s * (1.f / DM);
    float var = ss * (1.f / DM) - mu * mu;
    float inv = rsqrtf(var + 1e-5f);
    float s2 = 0.f, ss2 = 0.f;
    #pragma unroll
    for (int i = 0; i < 8; i++) {
        int d = threadIdx.x + i * 256;
        float bn = (loc[i] - mu) * inv * ln2g[d] + ln2b[d];
        loc[i] = bn; s2 += bn; ss2 += bn * bn;
    }
    s2  = block_sum_256(s2, sm);
    ss2 = block_sum_256(ss2, sm);
    float mu2  = s2 * (1.f / DM);
    float var2 = ss2 * (1.f / DM) - mu2 * mu2;
    float inv2 = rsqrtf(var2 + 1e-5f);
    #pragma unroll
    for (int i = 0; i < 8; i++) {
        int d = threadIdx.x + i * 256;
        float v = (loc[i] - mu2) * inv2 * fing[d] + finb[d];
        g_x3f[(size_t)t * DM + d] = __float2half_rn(v);
    }
}

__global__ void aux_write_k(float* out, int out_size) {
    if (out_size > SQ * VOC) out[(size_t)SQ * VOC] = g_aux;
}

// ---------------- launch ----------------
extern "C" void kernel_launch(void* const* d_in, const int* in_sizes, int n_in,
                              void* d_out, int out_size) {
    const int*   tokens = (const int*)d_in[0];
    const float* emb    = (const float*)d_in[1];
    const float* wq     = (const float*)d_in[2];
    const float* wk     = (const float*)d_in[3];
    const float* wv     = (const float*)d_in[4];
    const float* wo     = (const float*)d_in[5];
    const float* ln1_g  = (const float*)d_in[6];
    const float* ln1_b  = (const float*)d_in[7];
    const float* gate_w = (const float*)d_in[8];
    const float* w1     = (const float*)d_in[9];
    const float* w2     = (const float*)d_in[10];
    const float* w3     = (const float*)d_in[11];
    const float* ln2_g  = (const float*)d_in[12];
    const float* ln2_b  = (const float*)d_in[13];
    const float* fin_g  = (const float*)d_in[14];
    const float* fin_b  = (const float*)d_in[15];
    const float* head_w = (const float*)d_in[16];
    float* out = (float*)d_out;

    cudaFuncSetAttribute(mma_gemm, cudaFuncAttributeMaxDynamicSharedMemorySize, GSMEM_BYTES);
    cudaFuncSetAttribute(mma_gemm_f16, cudaFuncAttributeMaxDynamicSharedMemorySize, FSMEM_BYTES);

    float *p_x, *p_qkv, *p_x1, *p_x2, *p_h1, *p_y;
    __nv_bfloat16 *p_xh, *p_xl, *p_ath, *p_atl, *p_x2h, *p_x2l, *p_hh, *p_hl;
    __nv_bfloat16 *p_wqkvh, *p_wqkvl, *p_woh, *p_wol, *p_w1h, *p_w1l, *p_w3h, *p_w3l, *p_w2h, *p_w2l;
    __half *p_x3f, *p_hwf;
    int *p_etok;
    cudaGetSymbolAddress((void**)&p_x, g_x);     cudaGetSymbolAddress((void**)&p_qkv, g_qkv);
    cudaGetSymbolAddress((void**)&p_x1, g_x1);   cudaGetSymbolAddress((void**)&p_x2, g_x2);
    cudaGetSymbolAddress((void**)&p_h1, g_h1);   cudaGetSymbolAddress((void**)&p_y, g_y);
    cudaGetSymbolAddress((void**)&p_xh, g_xh);   cudaGetSymbolAddress((void**)&p_xl, g_xl);
    cudaGetSymbolAddress((void**)&p_ath, g_ath); cudaGetSymbolAddress((void**)&p_atl, g_atl);
    cudaGetSymbolAddress((void**)&p_x2h, g_x2h); cudaGetSymbolAddress((void**)&p_x2l, g_x2l);
    cudaGetSymbolAddress((void**)&p_x3f, g_x3f);
    cudaGetSymbolAddress((void**)&p_hh, g_hh);   cudaGetSymbolAddress((void**)&p_hl, g_hl);
    cudaGetSymbolAddress((void**)&p_wqkvh, g_wqkvh); cudaGetSymbolAddress((void**)&p_wqkvl, g_wqkvl);
    cudaGetSymbolAddress((void**)&p_woh, g_woh); cudaGetSymbolAddress((void**)&p_wol, g_wol);
    cudaGetSymbolAddress((void**)&p_w1h, g_w1h); cudaGetSymbolAddress((void**)&p_w1l, g_w1l);
    cudaGetSymbolAddress((void**)&p_w3h, g_w3h); cudaGetSymbolAddress((void**)&p_w3l, g_w3l);
    cudaGetSymbolAddress((void**)&p_w2h, g_w2h); cudaGetSymbolAddress((void**)&p_w2l, g_w2l);
    cudaGetSymbolAddress((void**)&p_hwf, g_hwf);
    cudaGetSymbolAddress((void**)&p_etok, g_etok);

    const int CVB = 1184, CVT = 256;
    cvt_split_k<<<CVB, CVT>>>((const float4*)wq, (uint4*)p_wqkvh,            (uint4*)p_wqkvl,            (long)DM*DM/8);
    cvt_split_k<<<CVB, CVT>>>((const float4*)wk, (uint4*)(p_wqkvh + DM*DM),  (uint4*)(p_wqkvl + DM*DM),  (long)DM*DM/8);
    cvt_split_k<<<CVB, CVT>>>((const float4*)wv, (uint4*)(p_wqkvh + 2*DM*DM),(uint4*)(p_wqkvl + 2*DM*DM),(long)DM*DM/8);
    embed_k<<<SQ, 256>>>(tokens, emb);
    ropetab_k<<<SQ, 32>>>();
    init_moe_k<<<1, 32>>>();

    // fused QKV: [1024 x 6144]
    mma_gemm<<<dim3(8, QKVN/128, 1), 256, GSMEM_BYTES>>>(p_xh, p_xl, p_wqkvh, p_wqkvl,
        p_qkv, nullptr, nullptr, nullptr, nullptr, nullptr, SQ, QKVN, DM, QKVN, 0, 0, 0);

    rope_k<<<SQ, 1024>>>();
    attn_k<<<dim3(NH, NBLK), 256>>>();

    // O-proj + residual
    cvt_split_k<<<CVB, CVT>>>((const float4*)wo, (uint4*)p_woh, (uint4*)p_wol, (long)DM*DM/8);
    mma_gemm<<<dim3(8, DM/128, 1), 256, GSMEM_BYTES>>>(p_ath, p_atl, p_woh, p_wol,
        p_x1, p_x, nullptr, nullptr, nullptr, nullptr, SQ, DM, DM, DM, 0, 0, 0);
    layernorm_k<<<SQ, 256>>>(p_x1, ln1_g, ln1_b, p_x2, p_x2h, p_x2l);

    gate_k<<<SQ, 128>>>(p_x2, gate_w);

    // MoE: w1 -> h1 fp32, w3 with fused silu -> split h, w2 -> y
    cvt_split_k<<<CVB, CVT>>>((const float4*)w1, (uint4*)p_w1h, (uint4*)p_w1l, (long)NE*DF*DM/8);
    mma_gemm<<<dim3(8, DF/128, NE), 256, GSMEM_BYTES>>>(p_x2h, p_x2l, p_w1h, p_w1l,
        p_h1, nullptr, nullptr, nullptr, nullptr, p_etok, -1, DF, DM, DF, 0, (long)DF*DM, (long)SQ*DF);
    cvt_split_k<<<CVB, CVT>>>((const float4*)w3, (uint4*)p_w3h, (uint4*)p_w3l, (long)NE*DF*DM/8);
    mma_gemm<<<dim3(8, DF/128, NE), 256, GSMEM_BYTES>>>(p_x2h, p_x2l, p_w3h, p_w3l,
        nullptr, nullptr, p_h1, p_hh, p_hl, p_etok, -1, DF, DM, DF, 0, (long)DF*DM, (long)SQ*DF);
    cvt_split_k<<<CVB, CVT>>>((const float4*)w2, (uint4*)p_w2h, (uint4*)p_w2l, (long)NE*DM*DF/8);
    mma_gemm<<<dim3(8, DM/128, NE), 256, GSMEM_BYTES>>>(p_hh, p_hl, p_w2h, p_w2l,
        p_y, nullptr, nullptr, nullptr, nullptr, nullptr, -1, DM, DF, DM, (long)SQ*DF, (long)DM*DF, (long)SQ*DM);

    combine_ln_k<<<SQ, 256>>>(p_y, p_x2, ln2_g, ln2_b, fin_g, fin_b);

    // head: fp16 single-MMA (terminal GEMM, error does not chain)
    cvt_f16_k<<<CVB, CVT>>>((const float4*)head_w, (uint4*)p_hwf, (long)VOC*DM/8);
    mma_gemm_f16<<<dim3(8, (VOC + 127)/128, 1), 256, FSMEM_BYTES>>>(p_x3f, p_hwf,
        out, SQ, VOC, DM, VOC);
    aux_write_k<<<1, 1>>>(out, out_size);
}